// round 15
// baseline (speedup 1.0000x reference)
#include <cuda_runtime.h>
#include <cuda_fp16.h>

#define B_DIM 32
#define N_IN 1000000
#define N_OUT 500000
#define TILE_O 128
#define GS 132                                   // s_out stride: = 4 mod 32
#define T_TILES ((N_IN + 255) / 256)             // 3907
#define G_TILES ((N_OUT + TILE_O - 1) / TILE_O)  // 3907

// 64 MB transposed fp16 scratch: xt[i][b], 64B per input column i.
// Half h occupies bytes [32h, 32h+32) of each row.
__device__ __half g_xt[(size_t)N_IN * B_DIM];

// ---------------------------------------------------------------------------
// Transpose one batch-half: x rows [16h,16h+16) x 256 input cols per tile.
// 256 threads: 4 independent LDG.128, conflict-free smem, 2 x 16B xt stores
// (32B = one sector per input column half: no write amplification).
// ---------------------------------------------------------------------------
__device__ __forceinline__ void transpose_half_tile(const float* __restrict__ x,
                                                    int h, int tile) {
    __shared__ float t16[16][257];
    const int t    = threadIdx.x;
    const int col0 = tile * 256;

    #pragma unroll
    for (int m = 0; m < 4; m++) {
        const int f   = m * 256 + t;
        const int row = f >> 6;        // 0..15
        const int qc  = f & 63;        // float4 col within tile
        const int c4  = col0 + 4 * qc;
        if (c4 < N_IN) {
            float4 v = __ldcs(reinterpret_cast<const float4*>(
                &x[(size_t)(16 * h + row) * N_IN + c4]));
            t16[row][4 * qc + 0] = v.x;
            t16[row][4 * qc + 1] = v.y;
            t16[row][4 * qc + 2] = v.z;
            t16[row][4 * qc + 3] = v.w;
        }
    }
    __syncthreads();

    #pragma unroll
    for (int m = 0; m < 2; m++) {
        const int e  = m * 256 + t;
        const int cc = e >> 1;         // 0..255 : input column within tile
        const int q  = e & 1;          // 8-element b_local chunk
        if (col0 + cc < N_IN) {
            __half2 h0 = __floats2half2_rn(t16[8 * q + 0][cc], t16[8 * q + 1][cc]);
            __half2 h1 = __floats2half2_rn(t16[8 * q + 2][cc], t16[8 * q + 3][cc]);
            __half2 h2 = __floats2half2_rn(t16[8 * q + 4][cc], t16[8 * q + 5][cc]);
            __half2 h3 = __floats2half2_rn(t16[8 * q + 6][cc], t16[8 * q + 7][cc]);
            uint4 u;
            u.x = *reinterpret_cast<unsigned*>(&h0);
            u.y = *reinterpret_cast<unsigned*>(&h1);
            u.z = *reinterpret_cast<unsigned*>(&h2);
            u.w = *reinterpret_cast<unsigned*>(&h3);
            *reinterpret_cast<uint4*>(
                &g_xt[(size_t)(col0 + cc) * B_DIM + 16 * h + 8 * q]) = u;
        }
    }
    __syncthreads();   // uniform per block (re-used smem safety for fused path)
}

// ---------------------------------------------------------------------------
// Gather one batch-half: 128 outputs per tile, 256 threads (8 warps).
// One LDG.128 serves 16 outputs: lane (g=lane>>1, s=lane&1) reads 16B =
// 8 halves (b_local = 8s..8s+7) of output base+g. Results staged with
// col ^ 16s swizzle (conflict-free STS and LDS.128); coalesced __stcs out.
// ---------------------------------------------------------------------------
__device__ __forceinline__ void gather_half_tile(const float* __restrict__ w,
                                                 const int*   __restrict__ idx,
                                                 float*       __restrict__ out,
                                                 int h, int tile) {
    __shared__ int2  sp[3 * TILE_O];
    __shared__ float so[16 * GS];

    const int tid  = threadIdx.x;
    const int warp = tid >> 5;
    const int lane = tid & 31;
    const int g    = lane >> 1;    // output within warp group (0..15)
    const int s    = lane & 1;     // 16B chunk: b_local = 8s..8s+7
    const int col0 = tile * TILE_O;

    #pragma unroll
    for (int m = 0; m < 2; m++) {
        const int e = m * 256 + tid;
        if (e < 3 * TILE_O) {
            const int gi = col0 * 3 + e;
            const bool v = (gi < 3 * N_OUT);
            sp[e] = make_int2(v ? __ldcs(&idx[gi]) : 0,
                              v ? __float_as_int(__ldcs(&w[gi])) : 0);
        }
    }
    __syncthreads();

    const int base = warp * 16;
    if (col0 + base < N_OUT) {     // tail is a multiple of 16 outputs
        const int ol = base + g;
        float acc[8] = {0, 0, 0, 0, 0, 0, 0, 0};
        #pragma unroll
        for (int k = 0; k < 3; k++) {
            const int2  p  = sp[ol * 3 + k];
            const float wk = __int_as_float(p.y);
            const uint4 v  = *reinterpret_cast<const uint4*>(
                &g_xt[(size_t)p.x * B_DIM + 16 * h + 8 * s]);
            const float2 f0 = __half22float2(*reinterpret_cast<const __half2*>(&v.x));
            const float2 f1 = __half22float2(*reinterpret_cast<const __half2*>(&v.y));
            const float2 f2 = __half22float2(*reinterpret_cast<const __half2*>(&v.z));
            const float2 f3 = __half22float2(*reinterpret_cast<const __half2*>(&v.w));
            acc[0] = fmaf(wk, f0.x, acc[0]);
            acc[1] = fmaf(wk, f0.y, acc[1]);
            acc[2] = fmaf(wk, f1.x, acc[2]);
            acc[3] = fmaf(wk, f1.y, acc[3]);
            acc[4] = fmaf(wk, f2.x, acc[4]);
            acc[5] = fmaf(wk, f2.y, acc[5]);
            acc[6] = fmaf(wk, f3.x, acc[6]);
            acc[7] = fmaf(wk, f3.y, acc[7]);
        }
        // bank = 4i + g + 16(warp&1 ^ s) : all 32 lanes distinct per STS.
        const int colsw = ol ^ (16 * s);
        #pragma unroll
        for (int i = 0; i < 8; i++) {
            so[(8 * s + i) * GS + colsw] = acc[i];
        }
    }
    __syncthreads();

    // Write 16 x 128 tile: 512 float4, 2/thread; coalesced __stcs.
    #pragma unroll
    for (int m = 0; m < 2; m++) {
        const int f4 = m * 256 + tid;
        const int b  = f4 >> 5;          // b_local 0..15
        const int c4 = (f4 & 31) * 4;
        const int oc = col0 + c4;
        if (oc < N_OUT) {
            const int cst = c4 ^ (16 * (b >> 3));   // un-swizzle, 16B aligned
            float4 vv = *reinterpret_cast<const float4*>(&so[b * GS + cst]);
            __stcs(reinterpret_cast<float4*>(
                &out[(size_t)(16 * h + b) * N_OUT + oc]), vv);
        }
    }
}

// ---------------------------------------------------------------------------
__global__ void __launch_bounds__(256) transpose_kernel(const float* __restrict__ x,
                                                        int h) {
    transpose_half_tile(x, h, blockIdx.x);
}

__global__ void __launch_bounds__(256) gather_kernel(const float* __restrict__ w,
                                                     const int*   __restrict__ idx,
                                                     float*       __restrict__ out,
                                                     int h) {
    gather_half_tile(w, idx, out, h, blockIdx.x);
}

// Fused middle stage: even blocks transpose half 1, odd blocks gather half 0.
// Parity interleave -> every resident wave mixes both traffic types.
__global__ void __launch_bounds__(256) fused_kernel(const float* __restrict__ x,
                                                    const float* __restrict__ w,
                                                    const int*   __restrict__ idx,
                                                    float*       __restrict__ out) {
    const int bid = blockIdx.x;
    if ((bid & 1) == 0) {
        transpose_half_tile(x, 1, bid >> 1);
    } else {
        gather_half_tile(w, idx, out, 0, bid >> 1);
    }
}

// ---------------------------------------------------------------------------
extern "C" void kernel_launch(void* const* d_in, const int* in_sizes, int n_in,
                              void* d_out, int out_size) {
    const float* x   = (const float*)d_in[0];   // (32, 1e6) fp32
    const float* w   = (const float*)d_in[1];   // (5e5, 3)  fp32
    const int*   idx = (const int*)  d_in[2];   // (5e5, 3)  int32
    float*       out = (float*)d_out;           // (32, 5e5) fp32

    transpose_kernel<<<T_TILES, 256>>>(x, 0);
    fused_kernel<<<T_TILES + G_TILES, 256>>>(x, w, idx, out);
    gather_kernel<<<G_TILES, 256>>>(w, idx, out, 1);
}

// round 17
// speedup vs baseline: 1.6600x; 1.6600x over previous
#include <cuda_runtime.h>
#include <cuda_fp16.h>

#define B_DIM 32
#define N_IN 1000000
#define N_OUT 500000
#define TILE_O 128
#define SOUT_STRIDE 132   // floats per b-row: = 4 mod 32, float4-aligned

// 64 MB transposed fp16 scratch: xt[i][b] -> one 64B line per input column i.
// Kept L2-resident: all other streams use evict-first hints.
__device__ __half g_xt[(size_t)N_IN * B_DIM];

// ---------------------------------------------------------------------------
// Kernel 1: transpose+convert x(32,1e6) fp32 -> xt(1e6,32) fp16.
// 32 x 128 tile per 256-thread block. Read: 4 LDG.128 + 4 STS.128 into an
// XOR-swizzled flat tile (stride 128 floats, 16B-granular swizzle
//   grp' = grp ^ (row&7) ^ 2*(row>>3)
// ). Write: 16 conflict-free LDS.32 + 2 STG.128 (fp16 pack).
// ---------------------------------------------------------------------------
__global__ void __launch_bounds__(256) transpose_kernel(const float* __restrict__ x) {
    __shared__ float tile[32 * 128];
    const int t    = threadIdx.x;
    const int col0 = blockIdx.x * 128;

    // Read: thread t loads rows {t>>5 + 8r}, float4 group qc = t&31. MLP=4.
    {
        const int row = t >> 5;
        const int qc  = t & 31;
        const int c4  = col0 + 4 * qc;
        if (c4 < N_IN) {
            #pragma unroll
            for (int r = 0; r < 4; r++) {
                const int rr = row + 8 * r;
                float4 v = __ldcs(reinterpret_cast<const float4*>(
                    &x[(size_t)rr * N_IN + c4]));
                const int grp = qc ^ (rr & 7) ^ (2 * (rr >> 3));
                *reinterpret_cast<float4*>(&tile[rr * 128 + 4 * grp]) = v;
            }
        }
    }
    __syncthreads();

    // Write: 512 16B xt chunks (row cc, b in [8qb, 8qb+8)); 2 per thread.
    // LDS bank = 4*(((cc>>2) ^ i ^ 2qb) & 7) + (cc&3) : all 32 distinct.
    #pragma unroll
    for (int m = 0; m < 2; m++) {
        const int e  = m * 256 + t;
        const int cc = e >> 2;     // 0..127 : column within tile
        const int qb = e & 3;      // 8-element b-chunk
        if (col0 + cc < N_IN) {
            float f[8];
            #pragma unroll
            for (int i = 0; i < 8; i++) {
                const int rr  = 8 * qb + i;
                const int grp = (cc >> 2) ^ (rr & 7) ^ (2 * (rr >> 3));
                f[i] = tile[rr * 128 + 4 * grp + (cc & 3)];
            }
            __half2 h0 = __floats2half2_rn(f[0], f[1]);
            __half2 h1 = __floats2half2_rn(f[2], f[3]);
            __half2 h2 = __floats2half2_rn(f[4], f[5]);
            __half2 h3 = __floats2half2_rn(f[6], f[7]);
            uint4 u;
            u.x = *reinterpret_cast<unsigned*>(&h0);
            u.y = *reinterpret_cast<unsigned*>(&h1);
            u.z = *reinterpret_cast<unsigned*>(&h2);
            u.w = *reinterpret_cast<unsigned*>(&h3);
            *reinterpret_cast<uint4*>(
                &g_xt[(size_t)(col0 + cc) * B_DIM + 8 * qb]) = u;   // keep in L2
        }
    }
}

// ---------------------------------------------------------------------------
// Kernel 2: gather-reduce (exact R11 structure, best measured: 29.2us).
// 256 threads (8 warps), 128 outputs per block. One LDG.128 serves 8 outputs:
// lane (g=l>>2, s=l&3) reads 16B = 8 halves (b=8s..8s+7) of output base+g.
// (idx,w) packed int2 in smem. Results staged b-major with XOR-swizzled
// columns; coalesced __stcs float4 writes.
// ---------------------------------------------------------------------------
__global__ void __launch_bounds__(256) gather_kernel(const float* __restrict__ w,
                                                     const int*   __restrict__ idx,
                                                     float*       __restrict__ out) {
    __shared__ int2  s_pair[3 * TILE_O];
    __shared__ float s_out[32 * SOUT_STRIDE];

    const int tid  = threadIdx.x;
    const int warp = tid >> 5;
    const int lane = tid & 31;
    const int g    = lane >> 2;   // output group (0..7)
    const int s    = lane & 3;    // 16B chunk: b = 8s..8s+7
    const int col0 = blockIdx.x * TILE_O;

    // Stage (idx, w) pairs for the tile, coalesced + evict-first.
    #pragma unroll
    for (int m = 0; m < 2; m++) {
        const int e = m * 256 + tid;
        if (e < 3 * TILE_O) {
            const int gi = col0 * 3 + e;
            const bool v = (gi < 3 * N_OUT);
            s_pair[e] = make_int2(v ? __ldcs(&idx[gi]) : 0,
                                  v ? __float_as_int(__ldcs(&w[gi])) : 0);
        }
    }
    __syncthreads();

    #pragma unroll
    for (int it = 0; it < 2; it++) {
        const int base = warp * 16 + it * 8;         // local output base
        if (col0 + base < N_OUT) {                   // N_OUT % 8 == 0
            const int ol = base + g;
            float acc[8] = {0, 0, 0, 0, 0, 0, 0, 0};
            #pragma unroll
            for (int k = 0; k < 3; k++) {
                const int2  p  = s_pair[ol * 3 + k];
                const float wk = __int_as_float(p.y);
                const uint4 v  = *reinterpret_cast<const uint4*>(
                    &g_xt[(size_t)p.x * B_DIM + 8 * s]);
                const float2 f0 = __half22float2(*reinterpret_cast<const __half2*>(&v.x));
                const float2 f1 = __half22float2(*reinterpret_cast<const __half2*>(&v.y));
                const float2 f2 = __half22float2(*reinterpret_cast<const __half2*>(&v.z));
                const float2 f3 = __half22float2(*reinterpret_cast<const __half2*>(&v.w));
                acc[0] = fmaf(wk, f0.x, acc[0]);
                acc[1] = fmaf(wk, f0.y, acc[1]);
                acc[2] = fmaf(wk, f1.x, acc[2]);
                acc[3] = fmaf(wk, f1.y, acc[3]);
                acc[4] = fmaf(wk, f2.x, acc[4]);
                acc[5] = fmaf(wk, f2.y, acc[5]);
                acc[6] = fmaf(wk, f3.x, acc[6]);
                acc[7] = fmaf(wk, f3.y, acc[7]);
            }
            // b-major staging, column XOR-swizzled by 8s (16B-granular).
            const int colsw = ol ^ (8 * s);
            #pragma unroll
            for (int i = 0; i < 8; i++) {
                s_out[(8 * s + i) * SOUT_STRIDE + colsw] = acc[i];
            }
        }
    }
    __syncthreads();

    // Write 32 x 128 tile: 1024 float4; conflict-free LDS.128, coalesced
    // STG.128 streamed past L2 (__stcs).
    #pragma unroll
    for (int m = 0; m < 4; m++) {
        const int f4 = m * 256 + tid;
        const int b  = f4 >> 5;
        const int c4 = (f4 & 31) * 4;
        const int oc = col0 + c4;
        if (oc < N_OUT) {
            const int cst = c4 ^ (8 * (b >> 3));   // un-swizzle (16B aligned)
            float4 vv = *reinterpret_cast<const float4*>(
                &s_out[b * SOUT_STRIDE + cst]);
            __stcs(reinterpret_cast<float4*>(&out[(size_t)b * N_OUT + oc]), vv);
        }
    }
}

// ---------------------------------------------------------------------------
extern "C" void kernel_launch(void* const* d_in, const int* in_sizes, int n_in,
                              void* d_out, int out_size) {
    const float* x   = (const float*)d_in[0];   // (32, 1e6) fp32
    const float* w   = (const float*)d_in[1];   // (5e5, 3)  fp32
    const int*   idx = (const int*)  d_in[2];   // (5e5, 3)  int32
    float*       out = (float*)d_out;           // (32, 5e5) fp32

    transpose_kernel<<<(N_IN + 127) / 128, 256>>>(x);
    gather_kernel<<<(N_OUT + TILE_O - 1) / TILE_O, 256>>>(w, idx, out);
}